// round 16
// baseline (speedup 1.0000x reference)
#include <cuda_runtime.h>
#include <math.h>

#define BATCH 4
#define NCLS 3
#define HH 96
#define WW 96
#define NPIX (HH * WW)           // 9216
#define NCOMBO 16                // batch(4) x class(2) x dir(2)
#define HCAP 1024                // histogram bins; d^2 >= HCAP -> overflow list
#define THREADS 1024
#define NWARP (THREADS / 32)     // 32
#define RS 4                     // column-slices per combo
#define SLICECOLS (WW / RS)      // 24
#define SLICEPIX (HH * SLICECOLS)// 2304
#define FULLMASK 0xffffffffu
#define FIELD_BLOCKS (NCOMBO * RS)   // 64
#define TOTAL_BLOCKS (FIELD_BLOCKS + NCOMBO)  // 80 (all co-resident on 148 SMs)

typedef unsigned long long u64;

// cross-kernel state
__device__ int g_hist[NCOMBO][HCAP];           // global histograms (zeroed by prep)
__device__ float g_stats[NCOMBO][3];           // {max, mean, percentile}
__device__ int g_cdone[NCOMBO];                // per-combo slice-done counters
__device__ int g_done;                         // combo-stats-done counter
__device__ int g_ovf_cnt[NCOMBO];
__device__ unsigned short g_ovf[NCOMBO][NPIX]; // overflow d^2 (expected unused)
__device__ unsigned g_mask[BATCH][2][2][HH][3];// [batch][pred/lab][class-1][row][third]

// nearest set-bit distance within a 96-bit row mask (cols 0-63 in lo, 64-95 in hi).
// returns >= 1000 if mask empty.
__device__ __forceinline__ int nearest_bit(u64 lo, unsigned hi, int cpos) {
    int dn = 1000, up = 1000;
    if (cpos < 64) {
        u64 m = lo >> cpos;                    // towards higher columns
        if (m) dn = __ffsll((long long)m) - 1;
        else if (hi) dn = 64 - cpos + __ffs((int)hi) - 1;
        u64 mu = lo << (63 - cpos);            // towards lower columns
        if (mu) up = __clzll((long long)mu);
    } else {
        unsigned m = hi >> (cpos - 64);
        if (m) dn = __ffs((int)m) - 1;
        unsigned mu = hi << (95 - cpos);
        if (mu) up = __clz((int)mu);
        else if (lo) up = (cpos - 64) + 1 + __clzll((long long)lo);
    }
    return min(dn, up);
}

// OR-reduce within aligned 8-lane groups (offsets 1,2,4 xor network)
__device__ __forceinline__ unsigned group8_or(unsigned v) {
    v |= __shfl_xor_sync(FULLMASK, v, 1);
    v |= __shfl_xor_sync(FULLMASK, v, 2);
    v |= __shfl_xor_sync(FULLMASK, v, 4);
    return v;
}

// ---------------------------------------------------------------------------
// Kernel 1 (prep): warp-per-row argmax with FLOAT4 loads + shuffle-assembled
// row bitmasks. 384 warps = 48 blocks x 256 threads. Also zeroes hist/counters.
// ---------------------------------------------------------------------------
#define PREP_THREADS 256
#define PREP_WARPS (PREP_THREADS / 32)            // 8
#define PREP_BLOCKS (BATCH * HH / PREP_WARPS)     // 48

__global__ __launch_bounds__(PREP_THREADS)
void prep_kernel(const float* __restrict__ preds,
                 const int* __restrict__ labels) {
    const int t = blockIdx.x * PREP_THREADS + threadIdx.x;
    for (int k = t; k < NCOMBO * HCAP; k += PREP_BLOCKS * PREP_THREADS)
        (&g_hist[0][0])[k] = 0;                   // 16384 / 12288 -> <=2 iters
    if (t < NCOMBO) { g_ovf_cnt[t] = 0; g_cdone[t] = 0; }
    if (t == NCOMBO) g_done = 0;

    const int w = t >> 5;                         // global warp = (batch, row)
    const int lane = t & 31;
    const int i = w / HH;
    const int r = w - i * HH;

    unsigned nibP1 = 0, nibP2 = 0, nibL1 = 0, nibL2 = 0;
    if (lane < 24) {                              // 24 quads of 4 px = 96 cols
        const float* base = preds + (size_t)i * NCLS * NPIX;
        const int qidx = (r * WW) / 4 + lane;
        float4 a = __ldg((const float4*)base + qidx);
        float4 b = __ldg((const float4*)(base + NPIX) + qidx);
        float4 d = __ldg((const float4*)(base + 2 * NPIX) + qidx);
        int4 L = __ldg((const int4*)(labels + i * NPIX) + qidx);
        float av[4] = {a.x, a.y, a.z, a.w};
        float bv4[4] = {b.x, b.y, b.z, b.w};
        float dv[4] = {d.x, d.y, d.z, d.w};
        int lv[4] = {L.x, L.y, L.z, L.w};
        #pragma unroll
        for (int u = 0; u < 4; u++) {
            int pc = 0; float bv = av[u];
            if (bv4[u] > bv) { bv = bv4[u]; pc = 1; }
            if (dv[u] > bv) pc = 2;
            nibP1 |= (pc == 1) << u;
            nibP2 |= (pc == 2) << u;
            nibL1 |= (lv[u] == 1) << u;
            nibL2 |= (lv[u] == 2) << u;
        }
    }
    const int sh = (lane & 7) * 4;
    unsigned wP1 = group8_or(nibP1 << sh);
    unsigned wP2 = group8_or(nibP2 << sh);
    unsigned wL1 = group8_or(nibL1 << sh);
    unsigned wL2 = group8_or(nibL2 << sh);
    if ((lane & 7) == 0 && lane < 24) {
        int th = lane >> 3;                       // row-third 0..2
        g_mask[i][0][0][r][th] = wP1;
        g_mask[i][0][1][r][th] = wP2;
        g_mask[i][1][0][r][th] = wL1;
        g_mask[i][1][1][r][th] = wL2;
    }
}

// ---------------------------------------------------------------------------
// Kernel 2 (field + stats, one launch, 80 co-resident blocks):
//   blocks 0..63: 16 combos x 4 column-slices. Mask load (2.3 KB), O(1)
//     along-row bit-scan g, vertical pass-2, warp-aggregated RED into hist;
//     last thread bumps g_cdone[c] (release).
//   blocks 64..79: stats for combo c = blockIdx.x-64. Spin until
//     g_cdone[c]==RS (all blocks resident -> deadlock-free), then the proven
//     reduction + percentile scan; last combo assembles the output.
// ---------------------------------------------------------------------------
__global__ __launch_bounds__(THREADS, 1)
void field_stats_kernel(float* __restrict__ out) {
    const int tid = threadIdx.x;
    const int lane = tid & 31;
    const int wid = tid >> 5;

    if (blockIdx.x < FIELD_BLOCKS) {
        // ---------------- field part ----------------
        __shared__ u64 s_slo[HH], s_tlo[HH];
        __shared__ unsigned s_shi[HH], s_thi[HH];
        __shared__ unsigned short g_s[SLICEPIX];

        const int c = blockIdx.x / RS;
        const int slice = blockIdx.x - c * RS;
        const int i = c >> 2;
        const int jc = (c >> 1) & 1;
        const int dir = c & 1;

        if (tid < 2 * HH) {
            const int m = tid / HH;                // 0 = source, 1 = target
            const int r = tid - m * HH;
            const int type = (m == 0) ? dir : (1 - dir);
            unsigned a0 = __ldg(&g_mask[i][type][jc][r][0]);
            unsigned a1 = __ldg(&g_mask[i][type][jc][r][1]);
            unsigned a2 = __ldg(&g_mask[i][type][jc][r][2]);
            u64 lo = (u64)a0 | ((u64)a1 << 32);
            if (m == 0) { s_slo[r] = lo; s_shi[r] = a2; }
            else        { s_tlo[r] = lo; s_thi[r] = a2; }
        }
        __syncthreads();

        const int c0 = slice * SLICECOLS;

        for (int idx = tid; idx < SLICEPIX; idx += THREADS) {
            int r = idx / SLICECOLS;
            int cc = c0 + (idx - r * SLICECOLS);
            int d = nearest_bit(s_tlo[r], s_thi[r], cc);
            d = min(d, 255);
            g_s[idx] = (unsigned short)(d * d);
        }
        __syncthreads();

        for (int idx = tid; idx < SLICEPIX; idx += THREADS) {
            int r = idx / SLICECOLS;
            int cc = c0 + (idx - r * SLICECOLS);
            bool valid = (cc < 64) ? ((s_slo[r] >> cc) & 1ull)
                                   : ((s_shi[r] >> (cc - 64)) & 1u);
            int best = -1;
            if (valid) {
                best = g_s[idx];
                if (best > 1) {
                    int v;
                    v = 1 + ((r - 1 >= 0) ? (int)g_s[idx - SLICECOLS] : 0x7fff); best = min(best, v);
                    v = 1 + ((r + 1 < HH) ? (int)g_s[idx + SLICECOLS] : 0x7fff); best = min(best, v);
                    v = 4 + ((r - 2 >= 0) ? (int)g_s[idx - 2 * SLICECOLS] : 0x7fff); best = min(best, v);
                    v = 4 + ((r + 2 < HH) ? (int)g_s[idx + 2 * SLICECOLS] : 0x7fff); best = min(best, v);
                    v = 9 + ((r - 3 >= 0) ? (int)g_s[idx - 3 * SLICECOLS] : 0x7fff); best = min(best, v);
                    v = 9 + ((r + 3 < HH) ? (int)g_s[idx + 3 * SLICECOLS] : 0x7fff); best = min(best, v);
                    for (int dr = 4; dr < HH; dr++) {
                        int d2 = dr * dr;
                        if (d2 >= best) break;
                        if (r - dr >= 0) { int vv = d2 + (int)g_s[idx - dr * SLICECOLS]; if (vv < best) best = vv; }
                        if (r + dr < HH) { int vv = d2 + (int)g_s[idx + dr * SLICECOLS]; if (vv < best) best = vv; }
                    }
                }
            }
            unsigned grp = __match_any_sync(FULLMASK, best);
            if (valid) {
                if (best < HCAP) {
                    if (lane == __ffs(grp) - 1) atomicAdd(&g_hist[c][best], __popc(grp));
                } else {
                    int pos = atomicAdd(&g_ovf_cnt[c], 1);
                    g_ovf[c][pos] = (unsigned short)min(best, 65535);
                }
            }
        }
        __syncthreads();
        if (tid == 0) {
            __threadfence();                       // release hist writes
            atomicAdd(&g_cdone[c], 1);
        }
        return;
    }

    // ---------------- stats part ----------------
    __shared__ int sh_hist[HCAP];
    __shared__ int s_n[NWARP];
    __shared__ float s_sum[NWARP];
    __shared__ int s_mx[NWARP];
    __shared__ int s_last;

    const int c = blockIdx.x - FIELD_BLOCKS;

    if (tid == 0) {
        volatile int* vc = &g_cdone[c];
        while (*vc < RS) __nanosleep(64);
    }
    __syncthreads();
    __threadfence();                               // acquire pairing

    int h = __ldcg(&g_hist[c][tid]);               // 1 iter (HCAP == THREADS)
    sh_hist[tid] = h;
    int n_loc = h;
    float sum_loc = h ? (float)h * sqrtf((float)tid) : 0.f;
    int mx_loc = h ? tid : 0;
    #pragma unroll
    for (int off = 16; off; off >>= 1) {
        n_loc += __shfl_down_sync(FULLMASK, n_loc, off);
        sum_loc += __shfl_down_sync(FULLMASK, sum_loc, off);
        mx_loc = max(mx_loc, __shfl_down_sync(FULLMASK, mx_loc, off));
    }
    if (lane == 0) { s_n[wid] = n_loc; s_sum[wid] = sum_loc; s_mx[wid] = mx_loc; }
    __syncthreads();
    if (wid == 0) {
        int n2 = s_n[lane];
        float sm2 = s_sum[lane];
        int mx2 = s_mx[lane];
        #pragma unroll
        for (int off = 16; off; off >>= 1) {
            n2 += __shfl_down_sync(FULLMASK, n2, off);
            sm2 += __shfl_down_sync(FULLMASK, sm2, off);
            mx2 = max(mx2, __shfl_down_sync(FULLMASK, mx2, off));
        }
        if (lane == 0) { s_n[0] = n2; s_sum[0] = sm2; s_mx[0] = mx2; }
    }
    __syncthreads();

    if (wid == 0) {
        const int n_hist = s_n[0];
        const int maxd2 = s_mx[0];
        const int m = g_ovf_cnt[c];      // overflow entries (expected 0)
        const int n = n_hist + m;
        float vlo = 0.f, vhi = 0.f;
        int lo = 0, hi = 0;
        float frac = 0.f;
        bool gotlo = false, gothi = false;
        if (n > 0) {
            float pos = 0.95f * (float)(n - 1);
            lo = (int)floorf(pos);
            hi = (int)ceilf(pos);
            frac = pos - (float)lo;
            int base = 0;
            for (int b0 = 0; b0 <= maxd2 && !gothi; b0 += 32) {
                int bb = b0 + lane;
                int hh = (bb < HCAP) ? sh_hist[bb] : 0;
                int cum = hh;
                #pragma unroll
                for (int off = 1; off < 32; off <<= 1) {
                    int v = __shfl_up_sync(FULLMASK, cum, off);
                    if (lane >= off) cum += v;
                }
                int ct = base + cum;
                unsigned mlo = __ballot_sync(FULLMASK, ct > lo);
                if (!gotlo && mlo) { vlo = sqrtf((float)(b0 + __ffs(mlo) - 1)); gotlo = true; }
                unsigned mhi = __ballot_sync(FULLMASK, ct > hi);
                if (!gothi && mhi) { vhi = sqrtf((float)(b0 + __ffs(mhi) - 1)); gothi = true; }
                base += __shfl_sync(FULLMASK, cum, 31);
            }
        }
        if (lane == 0) {
            float sum = s_sum[0];
            if (m > 0) {                 // exact slow path, correctness only
                for (int a = 0; a < m - 1; a++) {
                    int mi = a;
                    for (int b = a + 1; b < m; b++)
                        if (g_ovf[c][b] < g_ovf[c][mi]) mi = b;
                    unsigned short t2 = g_ovf[c][a];
                    g_ovf[c][a] = g_ovf[c][mi];
                    g_ovf[c][mi] = t2;
                }
                for (int a = 0; a < m; a++) sum += sqrtf((float)g_ovf[c][a]);
            }
            float mx = 0.f, mean = 0.f, pcl = 0.f;
            if (n > 0) {
                int truemax = (m > 0) ? (int)g_ovf[c][m - 1] : maxd2;
                mx = sqrtf((float)truemax);
                mean = sum / (float)n;
                if (!gotlo) vlo = sqrtf((float)g_ovf[c][lo - n_hist]);
                if (!gothi) vhi = sqrtf((float)g_ovf[c][hi - n_hist]);
                pcl = vlo * (1.0f - frac) + vhi * frac;
            }
            g_stats[c][0] = mx;
            g_stats[c][1] = mean;
            g_stats[c][2] = pcl;
            __threadfence();
            int t2 = atomicAdd(&g_done, 1);
            s_last = (t2 == NCOMBO - 1) ? 1 : 0;
        }
    }
    __syncthreads();

    // last combo assembles the output
    if (s_last && tid == 0) {
        __threadfence();
        float st[NCOMBO * 3];
        #pragma unroll
        for (int k = 0; k < NCOMBO * 3; k++)
            st[k] = *((volatile float*)&g_stats[0][0] + k);
        float M[3][5] = {{0}}, F[3][5] = {{0}}, R[3][5] = {{0}};
        for (int bi = 0; bi < BATCH; bi++) {
            for (int jj = 0; jj < 2; jj++) {
                int jjc = jj + 1;
                int cf = (bi << 2) | (jj << 1);
                int cr = cf | 1;
                float fmx = st[cf * 3 + 0], rmx = st[cr * 3 + 0];
                float fme = st[cf * 3 + 1], rme = st[cr * 3 + 1];
                float fp  = st[cf * 3 + 2], rp  = st[cr * 3 + 2];
                F[0][jjc] += fmx; R[0][jjc] += rmx; M[0][jjc] += fmaxf(fmx, rmx);
                F[1][jjc] += fme; R[1][jjc] += rme; M[1][jjc] += fmaxf(fme, rme);
                // faithful to source bug: FHD gets both directions' percentiles,
                // RHD percentile row stays zero
                F[2][jjc] += fp + rp;
                M[2][jjc] += fmaxf(fp, rp);
            }
        }
        float* mats[3] = {&M[0][0], &F[0][0], &R[0][0]};
        for (int t3 = 0; t3 < 3; t3++) {
            float* X = mats[t3];
            for (int r = 0; r < 3; r++) {
                for (int c2 = 0; c2 < 3; c2++) X[r * 5 + c2] *= 0.25f;  // / batch
                X[r * 5 + 3] = (X[r * 5 + 0] + X[r * 5 + 1] + X[r * 5 + 2]) / 3.0f;
                X[r * 5 + 4] = (X[r * 5 + 1] + X[r * 5 + 2]) * 0.5f;
            }
            for (int k = 0; k < 15; k++) out[t3 * 15 + k] = X[k];
        }
    }
}

// ---------------------------------------------------------------------------
extern "C" void kernel_launch(void* const* d_in, const int* in_sizes, int n_in,
                              void* d_out, int out_size) {
    const float* preds = (const float*)d_in[0];
    const int* labels = (const int*)d_in[1];
    float* out = (float*)d_out;

    prep_kernel<<<PREP_BLOCKS, PREP_THREADS>>>(preds, labels);
    field_stats_kernel<<<TOTAL_BLOCKS, THREADS>>>(out);
}

// round 17
// speedup vs baseline: 1.1152x; 1.1152x over previous
#include <cuda_runtime.h>
#include <math.h>

#define BATCH 4
#define NCLS 3
#define HH 96
#define WW 96
#define NPIX (HH * WW)           // 9216
#define NCOMBO 16                // batch(4) x class(2) x dir(2)
#define HCAP 1024                // histogram bins; d^2 >= HCAP -> overflow list
#define THREADS 1024
#define NWARP (THREADS / 32)     // 32
#define RS 4                     // column-slices per combo
#define SLICECOLS (WW / RS)      // 24
#define SLICEPIX (HH * SLICECOLS)// 2304
#define FULLMASK 0xffffffffu

typedef unsigned long long u64;

// cross-kernel state
__device__ int g_hist[NCOMBO][HCAP];           // global histograms (zeroed by prep)
__device__ float g_stats[NCOMBO][3];           // {max, mean, percentile}
__device__ int g_done;                         // last-block-done counter
__device__ int g_ovf_cnt[NCOMBO];
__device__ unsigned short g_ovf[NCOMBO][NPIX]; // overflow d^2 (expected unused)
__device__ unsigned g_mask[BATCH][2][2][HH][3];// [batch][pred/lab][class-1][row][third]

// nearest set-bit distance within a 96-bit row mask (cols 0-63 in lo, 64-95 in hi).
// returns >= 1000 if mask empty.
__device__ __forceinline__ int nearest_bit(u64 lo, unsigned hi, int cpos) {
    int dn = 1000, up = 1000;
    if (cpos < 64) {
        u64 m = lo >> cpos;                    // towards higher columns
        if (m) dn = __ffsll((long long)m) - 1;
        else if (hi) dn = 64 - cpos + __ffs((int)hi) - 1;
        u64 mu = lo << (63 - cpos);            // towards lower columns
        if (mu) up = __clzll((long long)mu);
    } else {
        unsigned m = hi >> (cpos - 64);
        if (m) dn = __ffs((int)m) - 1;
        unsigned mu = hi << (95 - cpos);
        if (mu) up = __clz((int)mu);
        else if (lo) up = (cpos - 64) + 1 + __clzll((long long)lo);
    }
    return min(dn, up);
}

// OR-reduce within aligned 8-lane groups (offsets 1,2,4 xor network)
__device__ __forceinline__ unsigned group8_or(unsigned v) {
    v |= __shfl_xor_sync(FULLMASK, v, 1);
    v |= __shfl_xor_sync(FULLMASK, v, 2);
    v |= __shfl_xor_sync(FULLMASK, v, 4);
    return v;
}

// ---------------------------------------------------------------------------
// Kernel 1 (prep): warp-per-row argmax with FLOAT4 loads + shuffle-assembled
// row bitmasks. 384 warps = 48 blocks x 256 threads. Also zeroes hist/counters.
// ---------------------------------------------------------------------------
#define PREP_THREADS 256
#define PREP_WARPS (PREP_THREADS / 32)            // 8
#define PREP_BLOCKS (BATCH * HH / PREP_WARPS)     // 48

__global__ __launch_bounds__(PREP_THREADS)
void prep_kernel(const float* __restrict__ preds,
                 const int* __restrict__ labels) {
    const int t = blockIdx.x * PREP_THREADS + threadIdx.x;
    for (int k = t; k < NCOMBO * HCAP; k += PREP_BLOCKS * PREP_THREADS)
        (&g_hist[0][0])[k] = 0;                   // 16384 / 12288 -> <=2 iters
    if (t < NCOMBO) g_ovf_cnt[t] = 0;
    if (t == NCOMBO) g_done = 0;

    const int w = t >> 5;                         // global warp = (batch, row)
    const int lane = t & 31;
    const int i = w / HH;
    const int r = w - i * HH;

    unsigned nibP1 = 0, nibP2 = 0, nibL1 = 0, nibL2 = 0;
    if (lane < 24) {                              // 24 quads of 4 px = 96 cols
        const float* base = preds + (size_t)i * NCLS * NPIX;
        const int qidx = (r * WW) / 4 + lane;
        float4 a = __ldg((const float4*)base + qidx);
        float4 b = __ldg((const float4*)(base + NPIX) + qidx);
        float4 d = __ldg((const float4*)(base + 2 * NPIX) + qidx);
        int4 L = __ldg((const int4*)(labels + i * NPIX) + qidx);
        float av[4] = {a.x, a.y, a.z, a.w};
        float bv4[4] = {b.x, b.y, b.z, b.w};
        float dv[4] = {d.x, d.y, d.z, d.w};
        int lv[4] = {L.x, L.y, L.z, L.w};
        #pragma unroll
        for (int u = 0; u < 4; u++) {
            int pc = 0; float bv = av[u];
            if (bv4[u] > bv) { bv = bv4[u]; pc = 1; }
            if (dv[u] > bv) pc = 2;
            nibP1 |= (pc == 1) << u;
            nibP2 |= (pc == 2) << u;
            nibL1 |= (lv[u] == 1) << u;
            nibL2 |= (lv[u] == 2) << u;
        }
    }
    const int sh = (lane & 7) * 4;
    unsigned wP1 = group8_or(nibP1 << sh);
    unsigned wP2 = group8_or(nibP2 << sh);
    unsigned wL1 = group8_or(nibL1 << sh);
    unsigned wL2 = group8_or(nibL2 << sh);
    if ((lane & 7) == 0 && lane < 24) {
        int th = lane >> 3;                       // row-third 0..2
        g_mask[i][0][0][r][th] = wP1;
        g_mask[i][0][1][r][th] = wP2;
        g_mask[i][1][0][r][th] = wL1;
        g_mask[i][1][1][r][th] = wL2;
    }
}

// ---------------------------------------------------------------------------
// Kernel 2 (field): 64 blocks = 16 combos x 4 COLUMN-slices.
// Front half: 2.3 KB mask load by 192 threads (no map copy, no sweeps).
// g = O(1) along-row bit-scan distance; pass-2 probes vertically in slice.
// Warp-aggregated RED.ADD into the global per-combo histogram.
// ---------------------------------------------------------------------------
__global__ __launch_bounds__(THREADS, 1)
void field_kernel() {
    __shared__ u64 s_slo[HH], s_tlo[HH];
    __shared__ unsigned s_shi[HH], s_thi[HH];
    __shared__ unsigned short g_s[SLICEPIX];   // [row][local col]

    const int c = blockIdx.x / RS;
    const int slice = blockIdx.x - c * RS;
    const int i = c >> 2;
    const int jc = (c >> 1) & 1;               // class index (class j = jc+1)
    const int dir = c & 1;
    const int tid = threadIdx.x;
    const int lane = tid & 31;

    // load row masks: 192 threads, one (map, row) each; 3 u32 loads apiece
    if (tid < 2 * HH) {
        const int m = tid / HH;                // 0 = source, 1 = target
        const int r = tid - m * HH;
        const int type = (m == 0) ? dir : (1 - dir);   // dir0: src=pred(0), tgt=lab(1)
        unsigned a0 = __ldg(&g_mask[i][type][jc][r][0]);
        unsigned a1 = __ldg(&g_mask[i][type][jc][r][1]);
        unsigned a2 = __ldg(&g_mask[i][type][jc][r][2]);
        u64 lo = (u64)a0 | ((u64)a1 << 32);
        if (m == 0) { s_slo[r] = lo; s_shi[r] = a2; }
        else        { s_tlo[r] = lo; s_thi[r] = a2; }
    }
    __syncthreads();

    const int c0 = slice * SLICECOLS;

    // g: O(1) along-row nearest-target distance squared, slice columns only
    for (int idx = tid; idx < SLICEPIX; idx += THREADS) {
        int r = idx / SLICECOLS;
        int cc = c0 + (idx - r * SLICECOLS);
        int d = nearest_bit(s_tlo[r], s_thi[r], cc);
        d = min(d, 255);
        g_s[idx] = (unsigned short)(d * d);
    }
    __syncthreads();

    // pass-2: vertical min with unconditional dr=1..3 window + pruned loop.
    for (int idx = tid; idx < SLICEPIX; idx += THREADS) {
        int r = idx / SLICECOLS;
        int cc = c0 + (idx - r * SLICECOLS);
        bool valid = (cc < 64) ? ((s_slo[r] >> cc) & 1ull)
                               : ((s_shi[r] >> (cc - 64)) & 1u);
        int best = -1;
        if (valid) {
            best = g_s[idx];
            if (best > 1) {
                int v;
                v = 1 + ((r - 1 >= 0) ? (int)g_s[idx - SLICECOLS] : 0x7fff); best = min(best, v);
                v = 1 + ((r + 1 < HH) ? (int)g_s[idx + SLICECOLS] : 0x7fff); best = min(best, v);
                v = 4 + ((r - 2 >= 0) ? (int)g_s[idx - 2 * SLICECOLS] : 0x7fff); best = min(best, v);
                v = 4 + ((r + 2 < HH) ? (int)g_s[idx + 2 * SLICECOLS] : 0x7fff); best = min(best, v);
                v = 9 + ((r - 3 >= 0) ? (int)g_s[idx - 3 * SLICECOLS] : 0x7fff); best = min(best, v);
                v = 9 + ((r + 3 < HH) ? (int)g_s[idx + 3 * SLICECOLS] : 0x7fff); best = min(best, v);
                for (int dr = 4; dr < HH; dr++) {
                    int d2 = dr * dr;
                    if (d2 >= best) break;
                    if (r - dr >= 0) { int vv = d2 + (int)g_s[idx - dr * SLICECOLS]; if (vv < best) best = vv; }
                    if (r + dr < HH) { int vv = d2 + (int)g_s[idx + dr * SLICECOLS]; if (vv < best) best = vv; }
                }
            }
        }
        // warp-aggregate equal bins: one global RED per distinct value per warp
        unsigned grp = __match_any_sync(FULLMASK, best);
        if (valid) {
            if (best < HCAP) {
                if (lane == __ffs(grp) - 1) atomicAdd(&g_hist[c][best], __popc(grp));
            } else {
                int pos = atomicAdd(&g_ovf_cnt[c], 1);
                g_ovf[c][pos] = (unsigned short)min(best, 65535);
            }
        }
    }
}

// ---------------------------------------------------------------------------
// Kernel 3 (stats): one block per combo; last finishing block assembles output.
// ---------------------------------------------------------------------------
__global__ __launch_bounds__(THREADS, 1)
void stats_kernel(float* __restrict__ out) {
    __shared__ int sh_hist[HCAP];
    __shared__ int s_n[NWARP];
    __shared__ float s_sum[NWARP];
    __shared__ int s_mx[NWARP];
    __shared__ int s_last;

    const int c = blockIdx.x;
    const int tid = threadIdx.x;
    const int lane = tid & 31;
    const int wid = tid >> 5;

    int h = __ldg(&g_hist[c][tid]);            // 1 iter (HCAP == THREADS)
    sh_hist[tid] = h;
    int n_loc = h;
    float sum_loc = h ? (float)h * sqrtf((float)tid) : 0.f;
    int mx_loc = h ? tid : 0;
    #pragma unroll
    for (int off = 16; off; off >>= 1) {
        n_loc += __shfl_down_sync(FULLMASK, n_loc, off);
        sum_loc += __shfl_down_sync(FULLMASK, sum_loc, off);
        mx_loc = max(mx_loc, __shfl_down_sync(FULLMASK, mx_loc, off));
    }
    if (lane == 0) { s_n[wid] = n_loc; s_sum[wid] = sum_loc; s_mx[wid] = mx_loc; }
    __syncthreads();
    if (wid == 0) {
        int n2 = s_n[lane];
        float sm2 = s_sum[lane];
        int mx2 = s_mx[lane];
        #pragma unroll
        for (int off = 16; off; off >>= 1) {
            n2 += __shfl_down_sync(FULLMASK, n2, off);
            sm2 += __shfl_down_sync(FULLMASK, sm2, off);
            mx2 = max(mx2, __shfl_down_sync(FULLMASK, mx2, off));
        }
        if (lane == 0) { s_n[0] = n2; s_sum[0] = sm2; s_mx[0] = mx2; }
    }
    __syncthreads();

    // warp 0 cooperative percentile scan, lane 0 finishes
    if (wid == 0) {
        const int n_hist = s_n[0];
        const int maxd2 = s_mx[0];
        const int m = g_ovf_cnt[c];      // overflow entries (expected 0)
        const int n = n_hist + m;
        float vlo = 0.f, vhi = 0.f;
        int lo = 0, hi = 0;
        float frac = 0.f;
        bool gotlo = false, gothi = false;
        if (n > 0) {
            float pos = 0.95f * (float)(n - 1);
            lo = (int)floorf(pos);
            hi = (int)ceilf(pos);
            frac = pos - (float)lo;
            int base = 0;
            for (int b0 = 0; b0 <= maxd2 && !gothi; b0 += 32) {
                int bb = b0 + lane;
                int hh = (bb < HCAP) ? sh_hist[bb] : 0;
                int cum = hh;
                #pragma unroll
                for (int off = 1; off < 32; off <<= 1) {
                    int v = __shfl_up_sync(FULLMASK, cum, off);
                    if (lane >= off) cum += v;
                }
                int ct = base + cum;
                unsigned mlo = __ballot_sync(FULLMASK, ct > lo);
                if (!gotlo && mlo) { vlo = sqrtf((float)(b0 + __ffs(mlo) - 1)); gotlo = true; }
                unsigned mhi = __ballot_sync(FULLMASK, ct > hi);
                if (!gothi && mhi) { vhi = sqrtf((float)(b0 + __ffs(mhi) - 1)); gothi = true; }
                base += __shfl_sync(FULLMASK, cum, 31);
            }
        }
        if (lane == 0) {
            float sum = s_sum[0];
            if (m > 0) {                 // exact slow path, correctness only
                for (int a = 0; a < m - 1; a++) {
                    int mi = a;
                    for (int b = a + 1; b < m; b++)
                        if (g_ovf[c][b] < g_ovf[c][mi]) mi = b;
                    unsigned short t = g_ovf[c][a];
                    g_ovf[c][a] = g_ovf[c][mi];
                    g_ovf[c][mi] = t;
                }
                for (int a = 0; a < m; a++) sum += sqrtf((float)g_ovf[c][a]);
            }
            float mx = 0.f, mean = 0.f, pcl = 0.f;
            if (n > 0) {
                int truemax = (m > 0) ? (int)g_ovf[c][m - 1] : maxd2;
                mx = sqrtf((float)truemax);
                mean = sum / (float)n;
                if (!gotlo) vlo = sqrtf((float)g_ovf[c][lo - n_hist]);
                if (!gothi) vhi = sqrtf((float)g_ovf[c][hi - n_hist]);
                pcl = vlo * (1.0f - frac) + vhi * frac;
            }
            g_stats[c][0] = mx;
            g_stats[c][1] = mean;
            g_stats[c][2] = pcl;
            __threadfence();
            int t = atomicAdd(&g_done, 1);
            s_last = (t == NCOMBO - 1) ? 1 : 0;
        }
    }
    __syncthreads();

    // last block assembles the output
    if (s_last && tid == 0) {
        __threadfence();
        float st[NCOMBO * 3];
        #pragma unroll
        for (int k = 0; k < NCOMBO * 3; k++)
            st[k] = *((volatile float*)&g_stats[0][0] + k);
        float M[3][5] = {{0}}, F[3][5] = {{0}}, R[3][5] = {{0}};
        for (int bi = 0; bi < BATCH; bi++) {
            for (int jj = 0; jj < 2; jj++) {
                int jjc = jj + 1;
                int cf = (bi << 2) | (jj << 1);
                int cr = cf | 1;
                float fmx = st[cf * 3 + 0], rmx = st[cr * 3 + 0];
                float fme = st[cf * 3 + 1], rme = st[cr * 3 + 1];
                float fp  = st[cf * 3 + 2], rp  = st[cr * 3 + 2];
                F[0][jjc] += fmx; R[0][jjc] += rmx; M[0][jjc] += fmaxf(fmx, rmx);
                F[1][jjc] += fme; R[1][jjc] += rme; M[1][jjc] += fmaxf(fme, rme);
                // faithful to source bug: FHD gets both directions' percentiles,
                // RHD percentile row stays zero
                F[2][jjc] += fp + rp;
                M[2][jjc] += fmaxf(fp, rp);
            }
        }
        float* mats[3] = {&M[0][0], &F[0][0], &R[0][0]};
        for (int t2 = 0; t2 < 3; t2++) {
            float* X = mats[t2];
            for (int r = 0; r < 3; r++) {
                for (int c2 = 0; c2 < 3; c2++) X[r * 5 + c2] *= 0.25f;  // / batch
                X[r * 5 + 3] = (X[r * 5 + 0] + X[r * 5 + 1] + X[r * 5 + 2]) / 3.0f;
                X[r * 5 + 4] = (X[r * 5 + 1] + X[r * 5 + 2]) * 0.5f;
            }
            for (int k = 0; k < 15; k++) out[t2 * 15 + k] = X[k];
        }
    }
}

// ---------------------------------------------------------------------------
extern "C" void kernel_launch(void* const* d_in, const int* in_sizes, int n_in,
                              void* d_out, int out_size) {
    const float* preds = (const float*)d_in[0];
    const int* labels = (const int*)d_in[1];
    float* out = (float*)d_out;

    prep_kernel<<<PREP_BLOCKS, PREP_THREADS>>>(preds, labels);
    field_kernel<<<NCOMBO * RS, THREADS>>>();
    stats_kernel<<<NCOMBO, THREADS>>>(out);
}